// round 7
// baseline (speedup 1.0000x reference)
#include <cuda_runtime.h>
#include <cstdint>

// Shapes fixed by the reference
#define B_   32
#define C_   256
#define HW_  4096
#define K_   32

#define THREADS 256
#define TILE_T  64
#define TILES_PER_BLOCK 8
#define CHUNK_T (TILE_T * TILES_PER_BLOCK)   // 512 tokens per block
#define NBLOCKS (B_ * (HW_ / CHUNK_T))       // 256 blocks -> 2 CTAs/SM

// ---- shared memory layout (float offsets) ----
// XCM[256][68]: x tile channel-major (raw f32; tf32 mma truncates). 68 % 32 == 4
// keeps both GEMM1 A-frag loads (banks 4q+g) and GEMM2 B-frag loads (banks
// 4g+q) conflict-free.
#define XCM_STRIDE 68
#define OFF_XCM 0
// WSX[64][40]: dual-use buffer. GEMM1 stores logits here (XCS role), softmax
// reads its own row then overwrites with tf32 weights (WS role) — reads
// strictly precede writes within the owning 4-lane group, so aliasing is safe.
// 40 % 32 == 8 -> GEMM2 A-frag banks 8q+g cover 32 distinct banks.
#define WSX_STRIDE 40
#define OFF_WSX  (256 * XCM_STRIDE)                  // 17408
// CWF: codeword B fragments pre-packed in (kt,nt,lane)->{b0,b1} order.
#define OFF_CWF  (OFF_WSX + TILE_T * WSX_STRIDE)     // 19968 (8192 floats)
#define OFF_XSQ  (OFF_CWF + 8192)                    // 28160 (64 floats)
#define OFF_CSQ  (OFF_XSQ + TILE_T)                  // 32
#define OFF_SCL  (OFF_CSQ + K_)                      // 32
#define OFF_WSM  (OFF_SCL + K_)                      // 32
#define SMEM_FLOATS (OFF_WSM + K_)                   // 28320
#define SMEM_BYTES  (SMEM_FLOATS * 4)                // 113280 B -> 2 CTAs/SM

__device__ float g_wsum[B_ * K_];

// cvt.rna.tf32.f32 requires a .b32 destination -> "=r" constraint.
__device__ __forceinline__ uint32_t tf32_bits(float x) {
    uint32_t r; asm("cvt.rna.tf32.f32 %0, %1;" : "=r"(r) : "f"(x)); return r;
}
__device__ __forceinline__ float to_tf32(float x) {
    return __uint_as_float(tf32_bits(x));
}
__device__ __forceinline__ uint32_t f2u(float x) { return __float_as_uint(x); }

// m16n8k8 tf32 mma, D += A*B (C aliased to D)
__device__ __forceinline__ void mma_tf32(float c[4],
                                         uint32_t a0, uint32_t a1, uint32_t a2, uint32_t a3,
                                         uint32_t b0, uint32_t b1) {
    asm volatile(
        "mma.sync.aligned.m16n8k8.row.col.f32.tf32.tf32.f32 "
        "{%0,%1,%2,%3}, {%4,%5,%6,%7}, {%8,%9}, {%0,%1,%2,%3};"
        : "+f"(c[0]), "+f"(c[1]), "+f"(c[2]), "+f"(c[3])
        : "r"(a0), "r"(a1), "r"(a2), "r"(a3), "r"(b0), "r"(b1));
}

__global__ void enc_zero(float* __restrict__ out) {
    int i = blockIdx.x * 256 + threadIdx.x;   // grid covers exactly B*K*C = 262144
    out[i] = 0.f;
    if (i < B_ * K_) g_wsum[i] = 0.f;
}

__global__ void __launch_bounds__(THREADS, 2)
enc_main(const float* __restrict__ x, const float* __restrict__ cw,
         const float* __restrict__ scale, float* __restrict__ out)
{
    extern __shared__ float sm[];
    float* XCM = sm + OFF_XCM;
    float* WSX = sm + OFF_WSX;
    float* CWF = sm + OFF_CWF;
    float* XSQ = sm + OFF_XSQ;
    float* CSQ = sm + OFF_CSQ;
    float* SCL = sm + OFF_SCL;
    float* WSM = sm + OFF_WSM;

    const int t    = threadIdx.x;
    const int w    = t >> 5;        // warp 0..7
    const int lane = t & 31;
    const int q    = lane & 3;      // mma thread-in-group
    const int g    = lane >> 2;     // mma group id

    const int b     = blockIdx.x >> 3;
    const int chunk = blockIdx.x & 7;
    const float* xb = x + (size_t)b * (C_ * HW_);

    // ---------------- prologue: scale, c_sq (f32), packed codeword frags ----
    if (t < K_) { SCL[t] = scale[t]; WSM[t] = 0.f; }
    {
        int code = t >> 3, p = t & 7;
        const float* cr = cw + code * C_ + p * 32;
        float s = 0.f;
        #pragma unroll
        for (int i = 0; i < 32; i++) s += cr[i] * cr[i];
        s += __shfl_xor_sync(0xffffffffu, s, 1);
        s += __shfl_xor_sync(0xffffffffu, s, 2);
        s += __shfl_xor_sync(0xffffffffu, s, 4);
        if (p == 0) CSQ[code] = s;
    }
    // B-frag packing: b0 = cw[nt*8 + lane/4][kt*8 + lane%4], b1 = +4 channels
    #pragma unroll
    for (int e = t; e < 4096; e += THREADS) {
        int kt = e >> 7, nt = (e >> 5) & 3, ln = e & 31;
        int code = nt * 8 + (ln >> 2);
        int ch   = kt * 8 + (ln & 3);
        float2 v;
        v.x = to_tf32(cw[code * C_ + ch]);
        v.y = to_tf32(cw[code * C_ + ch + 4]);
        *(float2*)(CWF + e * 2) = v;
    }

    // persistent GEMM2 accumulators: [mt codes16][ntl ch8][4]
    float acc[2][4][4];
    #pragma unroll
    for (int i = 0; i < 2; i++)
        #pragma unroll
        for (int j = 0; j < 4; j++)
            #pragma unroll
            for (int r = 0; r < 4; r++) acc[i][j][r] = 0.f;
    float wsum_acc[8];
    #pragma unroll
    for (int j = 0; j < 8; j++) wsum_acc[j] = 0.f;

    for (int tile = 0; tile < TILES_PER_BLOCK; tile++) {
        const int n0 = chunk * CHUNK_T + tile * TILE_T;

        __syncthreads();                 // prev GEMM2 done with XCM/WSX
        if (t < TILE_T) XSQ[t] = 0.f;
        __syncthreads();

        // ---------- Phase A: gmem -> smem channel-major + f32 x_sq ---------
        // Raw f32 into XCM: the tf32 mma truncates mantissas in HW, so no cvt
        // needed in this hot loop; x_sq uses full precision regardless.
        {
            const int ch16 = t >> 4;           // 0..15
            const int seg  = t & 15;           // 4-token segment
            const float* src = xb + n0 + 4 * seg;
            float q0 = 0.f, q1 = 0.f, q2 = 0.f, q3 = 0.f;
            #pragma unroll
            for (int j = 0; j < 16; j++) {
                int c = j * 16 + ch16;
                float4 v = *(const float4*)(src + (size_t)c * HW_);
                q0 += v.x * v.x; q1 += v.y * v.y;
                q2 += v.z * v.z; q3 += v.w * v.w;
                *(float4*)(XCM + c * XCM_STRIDE + 4 * seg) = v;
            }
            atomicAdd(&XSQ[4 * seg + 0], q0);
            atomicAdd(&XSQ[4 * seg + 1], q1);
            atomicAdd(&XSQ[4 * seg + 2], q2);
            atomicAdd(&XSQ[4 * seg + 3], q3);
        }
        __syncthreads();

        // ---------- GEMM1: XC[64x32] = X * CW^T ----------------------------
        {
            const int mt = w >> 1, nh = w & 1;   // mt 0..3, nh 0..1
            float cfr[2][4] = {{0.f,0.f,0.f,0.f},{0.f,0.f,0.f,0.f}};
            const int tokA = mt * 16 + g;
            #pragma unroll 4
            for (int kt = 0; kt < 32; kt++) {
                const float* base = XCM + (kt * 8 + q) * XCM_STRIDE + tokA;
                uint32_t a0 = f2u(base[0]);
                uint32_t a1 = f2u(base[8]);
                uint32_t a2 = f2u(base[4 * XCM_STRIDE]);
                uint32_t a3 = f2u(base[4 * XCM_STRIDE + 8]);
                #pragma unroll
                for (int ntl = 0; ntl < 2; ntl++) {
                    int nt = nh * 2 + ntl;
                    float2 bv = *(const float2*)(CWF + ((kt * 4 + nt) * 32 + lane) * 2);
                    mma_tf32(cfr[ntl], a0, a1, a2, a3, f2u(bv.x), f2u(bv.y));
                }
            }
            #pragma unroll
            for (int ntl = 0; ntl < 2; ntl++) {
                int col = (nh * 2 + ntl) * 8 + q * 2;
                float* p0 = WSX + (mt * 16 + g) * WSX_STRIDE + col;
                *(float2*)p0 = make_float2(cfr[ntl][0], cfr[ntl][1]);
                *(float2*)(p0 + 8 * WSX_STRIDE) = make_float2(cfr[ntl][2], cfr[ntl][3]);
            }
        }
        __syncthreads();

        // ---------- softmax over K=32 per token (f32, in-place in WSX) -----
        {
            const int row = t >> 2, qq = t & 3;       // 4 lanes per token
            float4 va = *(const float4*)(WSX + row * WSX_STRIDE + qq * 8);
            float4 vb = *(const float4*)(WSX + row * WSX_STRIDE + qq * 8 + 4);
            float xc8[8] = {va.x, va.y, va.z, va.w, vb.x, vb.y, vb.z, vb.w};
            float xsq = XSQ[row];
            float lg[8], mx = -1e30f;
            #pragma unroll
            for (int j = 0; j < 8; j++) {
                int k = qq * 8 + j;
                lg[j] = SCL[k] * (xsq - 2.f * xc8[j] + CSQ[k]);
                mx = fmaxf(mx, lg[j]);
            }
            mx = fmaxf(mx, __shfl_xor_sync(0xffffffffu, mx, 1));
            mx = fmaxf(mx, __shfl_xor_sync(0xffffffffu, mx, 2));
            float ex[8], sum = 0.f;
            #pragma unroll
            for (int j = 0; j < 8; j++) { ex[j] = __expf(lg[j] - mx); sum += ex[j]; }
            sum += __shfl_xor_sync(0xffffffffu, sum, 1);
            sum += __shfl_xor_sync(0xffffffffu, sum, 2);
            float inv = __fdividef(1.f, sum);
            float wv[8];
            #pragma unroll
            for (int j = 0; j < 8; j++) {
                float v = ex[j] * inv;
                wsum_acc[j] += v;
                wv[j] = to_tf32(v);
            }
            *(float4*)(WSX + row * WSX_STRIDE + qq * 8)     = make_float4(wv[0], wv[1], wv[2], wv[3]);
            *(float4*)(WSX + row * WSX_STRIDE + qq * 8 + 4) = make_float4(wv[4], wv[5], wv[6], wv[7]);
        }
        __syncthreads();

        // ---------- GEMM2: WX[32x256] += W^T * X (register-resident) -------
        {
            const int cb = w * 32;                    // this warp's 32-channel strip
            #pragma unroll
            for (int kt = 0; kt < 8; kt++) {
                const float* wsb = WSX + (kt * 8 + q) * WSX_STRIDE;
                uint32_t aw[2][4];
                #pragma unroll
                for (int mt = 0; mt < 2; mt++) {
                    aw[mt][0] = f2u(wsb[mt * 16 + g]);
                    aw[mt][1] = f2u(wsb[mt * 16 + g + 8]);
                    aw[mt][2] = f2u(wsb[4 * WSX_STRIDE + mt * 16 + g]);
                    aw[mt][3] = f2u(wsb[4 * WSX_STRIDE + mt * 16 + g + 8]);
                }
                #pragma unroll
                for (int ntl = 0; ntl < 4; ntl++) {
                    const float* xp = XCM + (cb + ntl * 8 + g) * XCM_STRIDE + kt * 8;
                    uint32_t b0 = f2u(xp[q]);
                    uint32_t b1 = f2u(xp[q + 4]);
                    mma_tf32(acc[0][ntl], aw[0][0], aw[0][1], aw[0][2], aw[0][3], b0, b1);
                    mma_tf32(acc[1][ntl], aw[1][0], aw[1][1], aw[1][2], aw[1][3], b0, b1);
                }
            }
        }
    }

    // ---------------- epilogue: wsum reduce + wx scatter --------------------
    #pragma unroll
    for (int j = 0; j < 8; j++) {
        float v = wsum_acc[j];
        v += __shfl_xor_sync(0xffffffffu, v, 4);
        v += __shfl_xor_sync(0xffffffffu, v, 8);
        v += __shfl_xor_sync(0xffffffffu, v, 16);
        if (g == 0) atomicAdd(&WSM[q * 8 + j], v);
    }
    __syncthreads();
    if (t < K_) atomicAdd(&g_wsum[b * K_ + t], WSM[t]);

    float* ob = out + (size_t)b * (K_ * C_);
    #pragma unroll
    for (int mt = 0; mt < 2; mt++)
        #pragma unroll
        for (int ntl = 0; ntl < 4; ntl++) {
            int code = mt * 16 + g;
            int ch   = w * 32 + ntl * 8 + 2 * q;
            atomicAdd(ob + code * C_ + ch,           acc[mt][ntl][0]);
            atomicAdd(ob + code * C_ + ch + 1,       acc[mt][ntl][1]);
            atomicAdd(ob + (code + 8) * C_ + ch,     acc[mt][ntl][2]);
            atomicAdd(ob + (code + 8) * C_ + ch + 1, acc[mt][ntl][3]);
        }
}

__global__ void enc_finalize(float* __restrict__ out, const float* __restrict__ cw) {
    int i  = blockIdx.x * 256 + threadIdx.x;  // covers 262144
    int kc = i >> 8;                          // b*K + k
    int k  = kc & (K_ - 1);
    int c  = i & (C_ - 1);
    out[i] -= g_wsum[kc] * cw[k * C_ + c];
}

extern "C" void kernel_launch(void* const* d_in, const int* in_sizes, int n_in,
                              void* d_out, int out_size) {
    const float* x     = (const float*)d_in[0];
    const float* cwp   = (const float*)d_in[1];
    const float* scale = (const float*)d_in[2];
    float* out = (float*)d_out;

    // Idempotent, capture-safe (not a stream op); no static guard.
    cudaFuncSetAttribute(enc_main, cudaFuncAttributeMaxDynamicSharedMemorySize, SMEM_BYTES);

    enc_zero<<<(B_ * K_ * C_) / 256, 256>>>(out);
    enc_main<<<NBLOCKS, THREADS, SMEM_BYTES>>>(x, cwp, scale, out);
    enc_finalize<<<(B_ * K_ * C_) / 256, 256>>>(out, cwp);
}

// round 10
// speedup vs baseline: 1.0544x; 1.0544x over previous
#include <cuda_runtime.h>
#include <cstdint>

#define B_ 32
#define C_ 256
#define HW_ 4096
#define K_ 32
#define THREADS 256
#define TILE_T 32
#define TILES 16
#define NBLOCKS 256            // b*8 + chunk, 512 tokens per block

// ---- smem layout (float offsets) ----
#define XCM_STRIDE 36          // 36%32==4: G1-A banks 4q+g, G2-B banks 4g+q conflict-free
#define XCMSZ (C_ * XCM_STRIDE)       // 9216 floats = 36864 B  (FIX: C_, not TILE_T)
#define OFF_X0  0
#define OFF_X1  XCMSZ                 // 9216
#define WSX_STRIDE 40                 // 40%32==8: G2-A banks 8q+g conflict-free
#define OFF_WSX (2 * XCMSZ)           // 18432
#define OFF_CWF (OFF_WSX + TILE_T * WSX_STRIDE)   // 19712 (8192 floats)
#define OFF_XSQ (OFF_CWF + 8192)      // 27904 (32)
#define OFF_CSQ (OFF_XSQ + TILE_T)    // 27936
#define OFF_SCL (OFF_CSQ + K_)        // 27968
#define OFF_WSM (OFF_SCL + K_)        // 28000
#define SMEM_FLOATS (OFF_WSM + K_)    // 28032
#define SMEM_BYTES (SMEM_FLOATS * 4)  // 112128 -> 2 CTAs/SM

__device__ float g_part[NBLOCKS * K_ * C_];   // per-block wx partials
__device__ float g_wsp[NBLOCKS * K_];         // per-block wsum partials

__device__ __forceinline__ uint32_t tf32_bits(float x) {
    uint32_t r; asm("cvt.rna.tf32.f32 %0, %1;" : "=r"(r) : "f"(x)); return r;
}
__device__ __forceinline__ float to_tf32(float x) { return __uint_as_float(tf32_bits(x)); }
__device__ __forceinline__ uint32_t f2u(float x) { return __float_as_uint(x); }
__device__ __forceinline__ uint32_t smem_u32(const void* p) {
    uint32_t a; asm("{ .reg .u64 t; cvta.to.shared.u64 t, %1; cvt.u32.u64 %0, t; }" : "=r"(a) : "l"(p));
    return a;
}
__device__ __forceinline__ void mma_tf32(float c[4],
        uint32_t a0, uint32_t a1, uint32_t a2, uint32_t a3, uint32_t b0, uint32_t b1) {
    asm volatile("mma.sync.aligned.m16n8k8.row.col.f32.tf32.tf32.f32 "
        "{%0,%1,%2,%3}, {%4,%5,%6,%7}, {%8,%9}, {%0,%1,%2,%3};"
        : "+f"(c[0]), "+f"(c[1]), "+f"(c[2]), "+f"(c[3])
        : "r"(a0), "r"(a1), "r"(a2), "r"(a3), "r"(b0), "r"(b1));
}
// one 32KB X tile: 2048 x 16B cp.async, 8 per thread
__device__ __forceinline__ void stage_tile(uint32_t sb, uint32_t buf_f4, const float* xb,
                                           int n0, int t) {
    #pragma unroll
    for (int i = 0; i < 8; i++) {
        int e = t + i * THREADS;              // 0..2047
        int ch = e >> 3, seg = e & 7;         // 8 x 4-token segments per channel
        uint32_t dst = sb + buf_f4 + (uint32_t)(ch * (XCM_STRIDE * 4) + seg * 16);
        const float* src = xb + (size_t)ch * HW_ + n0 + seg * 4;
        asm volatile("cp.async.cg.shared.global [%0], [%1], 16;" :: "r"(dst), "l"(src) : "memory");
    }
    asm volatile("cp.async.commit_group;" ::: "memory");
}

__global__ void __launch_bounds__(THREADS, 2)
enc_main(const float* __restrict__ x, const float* __restrict__ cw,
         const float* __restrict__ scale, float* __restrict__ out)
{
    extern __shared__ float sm[];
    float* WSX = sm + OFF_WSX;
    float* CWF = sm + OFF_CWF;
    float* XSQ = sm + OFF_XSQ;
    float* CSQ = sm + OFF_CSQ;
    float* SCL = sm + OFF_SCL;
    float* WSM = sm + OFF_WSM;
    const uint32_t sb = smem_u32(sm);

    const int t = threadIdx.x, w = t >> 5, lane = t & 31;
    const int q = lane & 3, g = lane >> 2;
    const int b = blockIdx.x >> 3, chunk = blockIdx.x & 7;
    const float* xb = x + (size_t)b * (C_ * HW_);
    const int base_n0 = chunk * (TILE_T * TILES);

    // ---- prologue ----
    if (t < K_) { SCL[t] = scale[t]; WSM[t] = 0.f; }
    {
        int code = t >> 3, p = t & 7;
        const float* cr = cw + code * C_ + p * 32;
        float s = 0.f;
        #pragma unroll
        for (int i = 0; i < 32; i++) s += cr[i] * cr[i];
        s += __shfl_xor_sync(~0u, s, 1); s += __shfl_xor_sync(~0u, s, 2); s += __shfl_xor_sync(~0u, s, 4);
        if (p == 0) CSQ[code] = s;
    }
    #pragma unroll
    for (int e = t; e < 4096; e += THREADS) {   // codeword B-frags
        int kt = e >> 7, nt = (e >> 5) & 3, ln = e & 31;
        int code = nt * 8 + (ln >> 2), ch = kt * 8 + (ln & 3);
        float2 v;
        v.x = to_tf32(cw[code * C_ + ch]);
        v.y = to_tf32(cw[code * C_ + ch + 4]);
        *(float2*)(CWF + e * 2) = v;
    }

    float acc[2][4][4];
    #pragma unroll
    for (int i = 0; i < 2; i++)
        #pragma unroll
        for (int j = 0; j < 4; j++)
            #pragma unroll
            for (int r = 0; r < 4; r++) acc[i][j][r] = 0.f;
    float wsum_acc[8];
    #pragma unroll
    for (int j = 0; j < 8; j++) wsum_acc[j] = 0.f;

    stage_tile(sb, OFF_X0 * 4, xb, base_n0, t);
    asm volatile("cp.async.wait_group 0;" ::: "memory");
    __syncthreads();

    for (int tile = 0; tile < TILES; tile++) {
        float* XC = sm + ((tile & 1) ? OFF_X1 : OFF_X0);
        if (tile + 1 < TILES)     // prefetch next tile into the other buffer
            stage_tile(sb, ((tile & 1) ? OFF_X0 : OFF_X1) * 4, xb,
                       base_n0 + (tile + 1) * TILE_T, t);

        // ---- G1: logits[32x32] = X * CW^T ; xsq piggybacked on A-frags ----
        {
            const int mt = w >> 2, nh = w & 3;     // M-tile 0..1, N-tile 0..3
            float cfr[4] = {0, 0, 0, 0};
            const int tokA = mt * 16 + g;
            float p0 = 0.f, p1 = 0.f;
            #pragma unroll 4
            for (int kt = 0; kt < 32; kt++) {
                const float* bp = XC + (kt * 8 + q) * XCM_STRIDE + tokA;
                float f0 = bp[0], f1 = bp[8];
                float f2 = bp[4 * XCM_STRIDE], f3 = bp[4 * XCM_STRIDE + 8];
                p0 += f0 * f0 + f2 * f2;
                p1 += f1 * f1 + f3 * f3;
                float2 bv = *(const float2*)(CWF + ((kt * 4 + nh) * 32 + lane) * 2);
                mma_tf32(cfr, f2u(f0), f2u(f1), f2u(f2), f2u(f3), f2u(bv.x), f2u(bv.y));
            }
            p0 += __shfl_xor_sync(~0u, p0, 1); p0 += __shfl_xor_sync(~0u, p0, 2);
            p1 += __shfl_xor_sync(~0u, p1, 1); p1 += __shfl_xor_sync(~0u, p1, 2);
            if (nh == 0 && q == 0) { XSQ[tokA] = p0; XSQ[tokA + 8] = p1; }
            int col = nh * 8 + q * 2;
            float* p = WSX + (mt * 16 + g) * WSX_STRIDE + col;
            *(float2*)p = make_float2(cfr[0], cfr[1]);
            *(float2*)(p + 8 * WSX_STRIDE) = make_float2(cfr[2], cfr[3]);
        }
        __syncthreads();

        // ---- softmax over K=32 (threads 0-127, in-place in WSX) ----
        if (t < 128) {
            const int row = t >> 2, qq = t & 3;
            float4 va = *(const float4*)(WSX + row * WSX_STRIDE + qq * 8);
            float4 vb = *(const float4*)(WSX + row * WSX_STRIDE + qq * 8 + 4);
            float xc8[8] = {va.x, va.y, va.z, va.w, vb.x, vb.y, vb.z, vb.w};
            float xsq = XSQ[row];
            float lg[8], mx = -1e30f;
            #pragma unroll
            for (int j = 0; j < 8; j++) {
                int k = qq * 8 + j;
                lg[j] = SCL[k] * (xsq - 2.f * xc8[j] + CSQ[k]);
                mx = fmaxf(mx, lg[j]);
            }
            mx = fmaxf(mx, __shfl_xor_sync(~0u, mx, 1));
            mx = fmaxf(mx, __shfl_xor_sync(~0u, mx, 2));
            float sum = 0.f;
            #pragma unroll
            for (int j = 0; j < 8; j++) { lg[j] = __expf(lg[j] - mx); sum += lg[j]; }
            sum += __shfl_xor_sync(~0u, sum, 1);
            sum += __shfl_xor_sync(~0u, sum, 2);
            float inv = __fdividef(1.f, sum);
            float wv[8];
            #pragma unroll
            for (int j = 0; j < 8; j++) {
                float v = lg[j] * inv;
                wsum_acc[j] += v;
                wv[j] = to_tf32(v);
            }
            *(float4*)(WSX + row * WSX_STRIDE + qq * 8)     = make_float4(wv[0], wv[1], wv[2], wv[3]);
            *(float4*)(WSX + row * WSX_STRIDE + qq * 8 + 4) = make_float4(wv[4], wv[5], wv[6], wv[7]);
        }
        __syncthreads();

        // ---- G2: WX[32x256] += W^T * X (register accumulators) ----
        {
            const int cb = w * 32;
            #pragma unroll
            for (int kt = 0; kt < 4; kt++) {
                const float* wsb = WSX + (kt * 8 + q) * WSX_STRIDE;
                uint32_t aw[2][4];
                #pragma unroll
                for (int mt = 0; mt < 2; mt++) {
                    aw[mt][0] = f2u(wsb[mt * 16 + g]);
                    aw[mt][1] = f2u(wsb[mt * 16 + g + 8]);
                    aw[mt][2] = f2u(wsb[4 * WSX_STRIDE + mt * 16 + g]);
                    aw[mt][3] = f2u(wsb[4 * WSX_STRIDE + mt * 16 + g + 8]);
                }
                #pragma unroll
                for (int ntl = 0; ntl < 4; ntl++) {
                    const float* xp = XC + (cb + ntl * 8 + g) * XCM_STRIDE + kt * 8;
                    uint32_t b0 = f2u(xp[q]), b1 = f2u(xp[q + 4]);
                    mma_tf32(acc[0][ntl], aw[0][0], aw[0][1], aw[0][2], aw[0][3], b0, b1);
                    mma_tf32(acc[1][ntl], aw[1][0], aw[1][1], aw[1][2], aw[1][3], b0, b1);
                }
            }
        }
        asm volatile("cp.async.wait_group 0;" ::: "memory");
        __syncthreads();
    }

    // ---- epilogue: private partials, no gmem atomics ----
    #pragma unroll
    for (int j = 0; j < 8; j++) {
        float v = wsum_acc[j];
        v += __shfl_xor_sync(~0u, v, 4); v += __shfl_xor_sync(~0u, v, 8); v += __shfl_xor_sync(~0u, v, 16);
        if (g == 0 && w < 4) atomicAdd(&WSM[q * 8 + j], v);
    }
    __syncthreads();
    if (t < K_) g_wsp[blockIdx.x * K_ + t] = WSM[t];

    float* pb = g_part + (size_t)blockIdx.x * (K_ * C_);
    #pragma unroll
    for (int mt = 0; mt < 2; mt++)
        #pragma unroll
        for (int ntl = 0; ntl < 4; ntl++) {
            int code = mt * 16 + g;
            int ch   = w * 32 + ntl * 8 + 2 * q;
            pb[code * C_ + ch]           = acc[mt][ntl][0];
            pb[code * C_ + ch + 1]       = acc[mt][ntl][1];
            pb[(code + 8) * C_ + ch]     = acc[mt][ntl][2];
            pb[(code + 8) * C_ + ch + 1] = acc[mt][ntl][3];
        }
}

__global__ void enc_finalize(float* __restrict__ out, const float* __restrict__ cw) {
    int i = blockIdx.x * 256 + threadIdx.x;          // covers 262144 = B*K*C
    int b = i >> 13, k = (i >> 8) & (K_ - 1), c = i & (C_ - 1);
    const float* pb = g_part + (size_t)(b * 8) * (K_ * C_) + k * C_ + c;
    const float* wp = g_wsp + b * 8 * K_ + k;
    float s = 0.f, ws = 0.f;
    #pragma unroll
    for (int ck = 0; ck < 8; ck++) {
        s  += pb[(size_t)ck * (K_ * C_)];
        ws += wp[ck * K_];
    }
    out[i] = s - ws * cw[k * C_ + c];
}

extern "C" void kernel_launch(void* const* d_in, const int* in_sizes, int n_in,
                              void* d_out, int out_size) {
    const float* x = (const float*)d_in[0];
    const float* cwp = (const float*)d_in[1];
    const float* scale = (const float*)d_in[2];
    float* out = (float*)d_out;
    cudaFuncSetAttribute(enc_main, cudaFuncAttributeMaxDynamicSharedMemorySize, SMEM_BYTES);
    enc_main<<<NBLOCKS, THREADS, SMEM_BYTES>>>(x, cwp, scale, out);
    enc_finalize<<<(B_ * K_ * C_) / 256, 256>>>(out, cwp);
}

// round 11
// speedup vs baseline: 1.3148x; 1.2470x over previous
#include <cuda_runtime.h>
#include <cuda_fp16.h>
#include <cstdint>

#define B_ 32
#define C_ 256
#define HW_ 4096
#define K_ 32
#define THREADS 256
#define TILE_T 32
#define TILES 16
#define NBLOCKS 256          // b*8 + chunk, 512 tokens per block

// ---- smem byte offsets ----
#define STG   0              // f32 staging [256 ch][36 f32]  (36864 B)
#define XROW  36864          // f16 [32 tok][264 half]        (16896 B)  stride 132 words
#define XCMO  53760          // f16 [256 ch][40 half]         (20480 B)  stride 20 words
#define CWC   74240          // f16 [32 code][264 half]       (16896 B)
#define WCO   91136          // f16 [32 code][40 half]        (2560 B)
#define LGO   93696          // f32 logits [32 tok][36]       (4608 B)
#define XSQP  98304          // f32 [8 seg][32 tok]           (1024 B)
#define CSQO  99328
#define SCLO  99456
#define WSMO  99584
#define SMEM_BYTES 99712     // -> 2 CTAs/SM

__device__ float g_part[NBLOCKS * K_ * C_];
__device__ float g_wsp[NBLOCKS * K_];

__device__ __forceinline__ uint32_t pk(float lo, float hi) {
    __half2 h = __floats2half2_rn(lo, hi);
    return *(uint32_t*)&h;
}
__device__ __forceinline__ uint32_t smem_u32(const void* p) {
    uint32_t a; asm("{ .reg .u64 t; cvta.to.shared.u64 t, %1; cvt.u32.u64 %0, t; }" : "=r"(a) : "l"(p));
    return a;
}
__device__ __forceinline__ void mma_f16(float c[4],
        uint32_t a0, uint32_t a1, uint32_t a2, uint32_t a3, uint32_t b0, uint32_t b1) {
    asm volatile("mma.sync.aligned.m16n8k16.row.col.f32.f16.f16.f32 "
        "{%0,%1,%2,%3}, {%4,%5,%6,%7}, {%8,%9}, {%0,%1,%2,%3};"
        : "+f"(c[0]), "+f"(c[1]), "+f"(c[2]), "+f"(c[3])
        : "r"(a0), "r"(a1), "r"(a2), "r"(a3), "r"(b0), "r"(b1));
}
// stage one 32-token X tile (32KB f32) into staging
__device__ __forceinline__ void stage_tile(uint32_t sb, const float* xb, int n0, int t) {
    #pragma unroll
    for (int i = 0; i < 8; i++) {
        int e = t + i * THREADS, ch = e >> 3, seg = e & 7;
        uint32_t dst = sb + STG + (uint32_t)(ch * 144 + seg * 16);
        const float* src = xb + (size_t)ch * HW_ + n0 + seg * 4;
        asm volatile("cp.async.cg.shared.global [%0], [%1], 16;" :: "r"(dst), "l"(src) : "memory");
    }
    asm volatile("cp.async.commit_group;" ::: "memory");
}

__global__ void __launch_bounds__(THREADS, 2)
enc_main(const float* __restrict__ x, const float* __restrict__ cw,
         const float* __restrict__ scale, float* __restrict__ out)
{
    extern __shared__ char base[];
    const uint32_t sb = smem_u32(base);
    float* STGf = (float*)(base + STG);
    uint32_t* XR = (uint32_t*)(base + XROW);
    uint32_t* XC2 = (uint32_t*)(base + XCMO);
    uint32_t* CW2 = (uint32_t*)(base + CWC);
    uint32_t* W2 = (uint32_t*)(base + WCO);
    __half* XCh = (__half*)(base + XCMO);
    __half* WCh = (__half*)(base + WCO);
    float* LG = (float*)(base + LGO);
    float* XQ = (float*)(base + XSQP);
    float* CSQ = (float*)(base + CSQO);
    float* SCL = (float*)(base + SCLO);
    float* WSM = (float*)(base + WSMO);

    const int t = threadIdx.x, w = t >> 5, lane = t & 31;
    const int q = lane & 3, g = lane >> 2;
    const int b = blockIdx.x >> 3, chunk = blockIdx.x & 7;
    const float* xb = x + (size_t)b * (C_ * HW_);
    const int base_n0 = chunk * (TILE_T * TILES);

    // ---- prologue ----
    if (t < K_) { SCL[t] = scale[t]; WSM[t] = 0.f; }
    {
        int code = t >> 3, p = t & 7;
        const float* cr = cw + code * C_ + p * 32;
        float s = 0.f;
        #pragma unroll
        for (int i = 0; i < 32; i++) s += cr[i] * cr[i];
        s += __shfl_xor_sync(~0u, s, 1); s += __shfl_xor_sync(~0u, s, 2); s += __shfl_xor_sync(~0u, s, 4);
        if (p == 0) CSQ[code] = s;
    }
    #pragma unroll
    for (int e = t; e < 4096; e += THREADS) {   // CW f16, pairs along ch
        int code = e >> 7, cp = e & 127;
        CW2[code * 132 + cp] = pk(cw[code * C_ + 2 * cp], cw[code * C_ + 2 * cp + 1]);
    }

    float acc[2][4][4];
    #pragma unroll
    for (int i = 0; i < 2; i++)
        #pragma unroll
        for (int j = 0; j < 4; j++)
            #pragma unroll
            for (int r = 0; r < 4; r++) acc[i][j][r] = 0.f;
    float wsum_acc[8];
    #pragma unroll
    for (int j = 0; j < 8; j++) wsum_acc[j] = 0.f;

    stage_tile(sb, xb, base_n0, t);

    for (int tile = 0; tile < TILES; tile++) {
        asm volatile("cp.async.wait_group 0;" ::: "memory");
        __syncthreads();                       // staging ready; f16 bufs free

        // ---- repack: staging f32 -> XROW/XCM f16 + raw-f32 xsq ----
        {
            const int tok = lane, seg = w;     // thread owns (token, 32-ch segment)
            float xq = 0.f;
            #pragma unroll
            for (int i = 0; i < 32; i += 2) {
                int c0 = seg * 32 + i;
                float v0 = STGf[c0 * 36 + tok];
                float v1 = STGf[(c0 + 1) * 36 + tok];
                xq += v0 * v0 + v1 * v1;
                XR[tok * 132 + seg * 16 + (i >> 1)] = pk(v0, v1);
                XCh[c0 * 40 + tok] = __float2half_rn(v0);
                XCh[(c0 + 1) * 40 + tok] = __float2half_rn(v1);
            }
            XQ[seg * 32 + tok] = xq;
        }
        __syncthreads();
        if (tile + 1 < TILES) stage_tile(sb, xb, base_n0 + (tile + 1) * TILE_T, t);

        // ---- G1: logits[32 tok x 32 code] = X * CW^T, K=256 (16 chunks) ----
        {
            const int mt = w >> 2, nh = w & 3;
            const int tokr = mt * 16 + g, crow = nh * 8 + g;
            float cfr[4] = {0, 0, 0, 0};
            #pragma unroll
            for (int kc = 0; kc < 16; kc++) {
                int kb = kc * 8 + q;
                uint32_t a0 = XR[tokr * 132 + kb];
                uint32_t a1 = XR[(tokr + 8) * 132 + kb];
                uint32_t a2 = XR[tokr * 132 + kb + 4];
                uint32_t a3 = XR[(tokr + 8) * 132 + kb + 4];
                uint32_t b0 = CW2[crow * 132 + kb];
                uint32_t b1 = CW2[crow * 132 + kb + 4];
                mma_f16(cfr, a0, a1, a2, a3, b0, b1);
            }
            int col = nh * 8 + 2 * q;
            *(float2*)(LG + tokr * 36 + col) = make_float2(cfr[0], cfr[1]);
            *(float2*)(LG + (tokr + 8) * 36 + col) = make_float2(cfr[2], cfr[3]);
        }
        __syncthreads();

        // ---- softmax per token (threads 0-127), W -> f16 [code][tok] ----
        if (t < 128) {
            const int row = t >> 2, qq = t & 3;
            float4 va = *(const float4*)(LG + row * 36 + qq * 8);
            float4 vb = *(const float4*)(LG + row * 36 + qq * 8 + 4);
            float xc8[8] = {va.x, va.y, va.z, va.w, vb.x, vb.y, vb.z, vb.w};
            float xsq = 0.f;
            #pragma unroll
            for (int s = 0; s < 8; s++) xsq += XQ[s * 32 + row];
            float lg[8], mx = -1e30f;
            #pragma unroll
            for (int j = 0; j < 8; j++) {
                int k = qq * 8 + j;
                lg[j] = SCL[k] * (xsq - 2.f * xc8[j] + CSQ[k]);
                mx = fmaxf(mx, lg[j]);
            }
            mx = fmaxf(mx, __shfl_xor_sync(~0u, mx, 1));
            mx = fmaxf(mx, __shfl_xor_sync(~0u, mx, 2));
            float sum = 0.f;
            #pragma unroll
            for (int j = 0; j < 8; j++) { lg[j] = __expf(lg[j] - mx); sum += lg[j]; }
            sum += __shfl_xor_sync(~0u, sum, 1);
            sum += __shfl_xor_sync(~0u, sum, 2);
            float inv = __fdividef(1.f, sum);
            #pragma unroll
            for (int j = 0; j < 8; j++) {
                float v = lg[j] * inv;
                wsum_acc[j] += v;
                WCh[(qq * 8 + j) * 40 + row] = __float2half_rn(v);
            }
        }
        __syncthreads();

        // ---- G2: D[256 ch x 32 code] += X^T * W, K=32 tok (2 chunks) ----
        {
            const int chb = w * 32;
            #pragma unroll
            for (int kc = 0; kc < 2; kc++) {
                int kb = kc * 8 + q;
                uint32_t bw[4][2];
                #pragma unroll
                for (int nt = 0; nt < 4; nt++) {
                    bw[nt][0] = W2[(nt * 8 + g) * 20 + kb];
                    bw[nt][1] = W2[(nt * 8 + g) * 20 + kb + 4];
                }
                #pragma unroll
                for (int mtc = 0; mtc < 2; mtc++) {
                    int chr = chb + mtc * 16 + g;
                    uint32_t a0 = XC2[chr * 20 + kb];
                    uint32_t a1 = XC2[(chr + 8) * 20 + kb];
                    uint32_t a2 = XC2[chr * 20 + kb + 4];
                    uint32_t a3 = XC2[(chr + 8) * 20 + kb + 4];
                    #pragma unroll
                    for (int nt = 0; nt < 4; nt++)
                        mma_f16(acc[mtc][nt], a0, a1, a2, a3, bw[nt][0], bw[nt][1]);
                }
            }
        }
        // (cp.async for tile+1 still in flight; waited at loop top)
    }

    // ---- epilogue ----
    if (t < 128) {
        #pragma unroll
        for (int j = 0; j < 8; j++) {
            float v = wsum_acc[j];
            v += __shfl_xor_sync(~0u, v, 4); v += __shfl_xor_sync(~0u, v, 8); v += __shfl_xor_sync(~0u, v, 16);
            if ((lane >> 2) == 0) atomicAdd(&WSM[(lane & 3) * 8 + j], v);
        }
    }
    __syncthreads();
    if (t < K_) g_wsp[blockIdx.x * K_ + t] = WSM[t];

    float* pb = g_part + (size_t)blockIdx.x * (K_ * C_);
    {
        const int chb = w * 32;
        #pragma unroll
        for (int mtc = 0; mtc < 2; mtc++)
            #pragma unroll
            for (int nt = 0; nt < 4; nt++) {
                int ch = chb + mtc * 16 + g;
                int code = nt * 8 + 2 * q;
                pb[code * C_ + ch]             = acc[mtc][nt][0];
                pb[(code + 1) * C_ + ch]       = acc[mtc][nt][1];
                pb[code * C_ + ch + 8]         = acc[mtc][nt][2];
                pb[(code + 1) * C_ + ch + 8]   = acc[mtc][nt][3];
            }
    }
}

__global__ void enc_finalize(float* __restrict__ out, const float* __restrict__ cw) {
    int i = blockIdx.x * 256 + threadIdx.x;          // covers 262144 = B*K*C
    int b = i >> 13, k = (i >> 8) & (K_ - 1), c = i & (C_ - 1);
    const float* pb = g_part + (size_t)(b * 8) * (K_ * C_) + k * C_ + c;
    const float* wp = g_wsp + b * 8 * K_ + k;
    float s = 0.f, ws = 0.f;
    #pragma unroll
    for (int ck = 0; ck < 8; ck++) {
        s  += pb[(size_t)ck * (K_ * C_)];
        ws += wp[ck * K_];
    }
    out[i] = s - ws * cw[k * C_ + c];
}

extern "C" void kernel_launch(void* const* d_in, const int* in_sizes, int n_in,
                              void* d_out, int out_size) {
    const float* x = (const float*)d_in[0];
    const float* cwp = (const float*)d_in[1];
    const float* scale = (const float*)d_in[2];
    float* out = (float*)d_out;
    cudaFuncSetAttribute(enc_main, cudaFuncAttributeMaxDynamicSharedMemorySize, SMEM_BYTES);
    enc_main<<<NBLOCKS, THREADS, SMEM_BYTES>>>(x, cwp, scale, out);
    enc_finalize<<<(B_ * K_ * C_) / 256, 256>>>(out, cwp);
}